// round 3
// baseline (speedup 1.0000x reference)
#include <cuda_runtime.h>
#include <stdint.h>
#include <math.h>

// ---------------------------------------------------------------------------
// out[b,o] = min_i ( x[b,i] + mask[o,i] ),  B=IN=OUT=512,  x in [0,1)
// mask in {0,1}  =>  out[b,o] = min over SELECTED i of x[b,i]  (sparse min).
// Selection = JAX threefry bernoulli (partitionable variant, validated R2).
// ---------------------------------------------------------------------------

#define B_DIM   512
#define IN_DIM  512
#define OUT_DIM 512
#define N_EDGES (OUT_DIM * IN_DIM)
#define SEL_WORDS (IN_DIM / 32)      // 16 words per o-row

__device__ uint32_t g_sel[OUT_DIM * SEL_WORDS];          // selection bitmask
__device__ unsigned long long g_topk[B_DIM * 64];        // sorted top-64 keys/row

// ---------------- Threefry-2x32 (constexpr) --------------------------------
struct TF2 { uint32_t a, b; };

__host__ __device__ constexpr uint32_t rotl32(uint32_t v, int r) {
    return (v << r) | (v >> (32 - r));
}

__host__ __device__ constexpr TF2 tf2x32(uint32_t k0, uint32_t k1,
                                         uint32_t x0, uint32_t x1) {
    uint32_t k2 = k0 ^ k1 ^ 0x1BD11BDAu;
    x0 += k0; x1 += k1;
    x0 += x1; x1 = rotl32(x1, 13) ^ x0;
    x0 += x1; x1 = rotl32(x1, 15) ^ x0;
    x0 += x1; x1 = rotl32(x1, 26) ^ x0;
    x0 += x1; x1 = rotl32(x1,  6) ^ x0;
    x0 += k1; x1 += k2 + 1u;
    x0 += x1; x1 = rotl32(x1, 17) ^ x0;
    x0 += x1; x1 = rotl32(x1, 29) ^ x0;
    x0 += x1; x1 = rotl32(x1, 16) ^ x0;
    x0 += x1; x1 = rotl32(x1, 24) ^ x0;
    x0 += k2; x1 += k0 + 2u;
    x0 += x1; x1 = rotl32(x1, 13) ^ x0;
    x0 += x1; x1 = rotl32(x1, 15) ^ x0;
    x0 += x1; x1 = rotl32(x1, 26) ^ x0;
    x0 += x1; x1 = rotl32(x1,  6) ^ x0;
    x0 += k0; x1 += k1 + 3u;
    x0 += x1; x1 = rotl32(x1, 17) ^ x0;
    x0 += x1; x1 = rotl32(x1, 29) ^ x0;
    x0 += x1; x1 = rotl32(x1, 16) ^ x0;
    x0 += x1; x1 = rotl32(x1, 24) ^ x0;
    x0 += k1; x1 += k2 + 4u;
    x0 += x1; x1 = rotl32(x1, 13) ^ x0;
    x0 += x1; x1 = rotl32(x1, 15) ^ x0;
    x0 += x1; x1 = rotl32(x1, 26) ^ x0;
    x0 += x1; x1 = rotl32(x1,  6) ^ x0;
    x0 += k2; x1 += k0 + 5u;
    return TF2{x0, x1};
}

// k_bern: foldlike split of key(42)=(0,42), row 0 -> threefry((0,42),(0,0))
constexpr TF2 KB = tf2x32(0u, 42u, 0u, 0u);

// ---------------- 1) selection bitmask --------------------------------------
__global__ __launch_bounds__(256) void mask_kernel(const float* __restrict__ pw) {
    uint32_t n = blockIdx.x * 256u + threadIdx.x;      // flat edge o*512+i

    TF2 r = tf2x32(KB.a, KB.b, 0u, n);
    uint32_t bits = r.a ^ r.b;
    float u = __uint_as_float((bits >> 9) | 0x3F800000u) - 1.0f;

    // selected <=> u < softmax(w)[1] <=> u*(1+exp(wx-wy)) < 1  (fp64, ~1e-16)
    float2 w = reinterpret_cast<const float2*>(pw)[n];
    double e = exp((double)w.x - (double)w.y);
    bool sel = ((double)u) * (1.0 + e) < 1.0;

    uint32_t word = __ballot_sync(0xFFFFFFFFu, sel);
    if ((threadIdx.x & 31u) == 0u) g_sel[n >> 5] = word;
}

// ---------------- 2) per-row bitonic sort, emit sorted top-64 ---------------
__global__ __launch_bounds__(256) void sort_kernel(const float* __restrict__ x) {
    __shared__ unsigned long long keys[512];
    const int row = blockIdx.x;
    const int t = threadIdx.x;

    for (int i = t; i < 512; i += 256) {
        uint32_t vb = __float_as_uint(x[row * IN_DIM + i]);   // x >= 0
        keys[i] = ((unsigned long long)vb << 32) | (unsigned)i;
    }

    for (int k = 2; k <= 512; k <<= 1) {
        for (int j = k >> 1; j > 0; j >>= 1) {
            __syncthreads();
            int i = 2 * t - (t & (j - 1));   // all i with (i & j) == 0
            int ixj = i | j;
            unsigned long long a = keys[i], b = keys[ixj];
            bool up = ((i & k) == 0);
            if ((a > b) == up) { keys[i] = b; keys[ixj] = a; }
        }
    }
    __syncthreads();
    if (t < 64) g_topk[row * 64 + t] = keys[t];
}

// ---------------- 3) gather: first selected index in sorted order -----------
// CTA covers 8 b-rows x 256 o-cols; grid (2, 64).
__global__ __launch_bounds__(256) void gather_kernel(
    const float* __restrict__ x, float* __restrict__ out) {
    __shared__ uint32_t s_sel[256][SEL_WORDS + 1];   // pad 17 -> conflict-free
    __shared__ unsigned long long s_keys[8][64];

    const int ob = blockIdx.x * 256;
    const int bb = blockIdx.y * 8;
    const int t = threadIdx.x;

    // load 256 sel rows (4096 words, coalesced)
#pragma unroll
    for (int q = 0; q < 16; ++q) {
        int flat = q * 256 + t;                     // == global word offset
        s_sel[flat >> 4][flat & 15] = g_sel[ob * SEL_WORDS + flat];
    }
    // load 8 rows of top-64 keys
#pragma unroll
    for (int q = 0; q < 2; ++q) {
        int flat = q * 256 + t;
        s_keys[flat >> 6][flat & 63] = g_topk[(bb + (flat >> 6)) * 64 + (flat & 63)];
    }
    __syncthreads();

    const uint32_t* selrow = s_sel[t];               // this thread's o-row
    const int o = ob + t;

#pragma unroll 1
    for (int bi = 0; bi < 8; ++bi) {
        float res = 0.0f;
        bool found = false;
        for (int j = 0; j < 64; ++j) {               // expected ~2 iterations
            unsigned long long key = s_keys[bi][j];
            unsigned idx = (unsigned)key & 511u;
            if ((selrow[idx >> 5] >> (idx & 31u)) & 1u) {
                res = __uint_as_float((uint32_t)(key >> 32));
                found = true;
                break;
            }
        }
        if (!found) {                                // P ~ 2e-9 per pair: exact fallback
            uint32_t best = 0x7F800000u;
            const float* xr = x + (bb + bi) * IN_DIM;
            for (int i = 0; i < IN_DIM; ++i)
                if ((selrow[i >> 5] >> (i & 31u)) & 1u) {
                    uint32_t vb = __float_as_uint(xr[i]);
                    best = best < vb ? best : vb;
                }
            if (best == 0x7F800000u)                 // zero selected: impossible
                best = __float_as_uint(
                    __uint_as_float((uint32_t)(s_keys[bi][0] >> 32)) + 1.0f);
            res = __uint_as_float(best);
        }
        out[(bb + bi) * OUT_DIM + o] = res;
    }
}

// ---------------------------------------------------------------------------
extern "C" void kernel_launch(void* const* d_in, const int* in_sizes, int n_in,
                              void* d_out, int out_size) {
    const float* x  = (const float*)d_in[0];   // [512, 512]
    const float* pw = (const float*)d_in[1];   // [512, 512, 2]
    float* out      = (float*)d_out;           // [512, 512]

    mask_kernel<<<N_EDGES / 256, 256>>>(pw);
    sort_kernel<<<B_DIM, 256>>>(x);
    dim3 ggrid(OUT_DIM / 256, B_DIM / 8);
    gather_kernel<<<ggrid, 256>>>(x, out);
}

// round 4
// speedup vs baseline: 2.6519x; 2.6519x over previous
#include <cuda_runtime.h>
#include <stdint.h>
#include <math.h>

// ---------------------------------------------------------------------------
// out[b,o] = min_i ( x[b,i] + mask[o,i] ),  B=IN=OUT=512,  x in [0,1)
// mask in {0,1}  =>  out[b,o] = min over SELECTED i of x[b,i]  (sparse min).
// Selection = JAX threefry bernoulli (partitionable variant, validated R2/R3).
// ---------------------------------------------------------------------------

#define B_DIM   512
#define IN_DIM  512
#define OUT_DIM 512
#define N_EDGES (OUT_DIM * IN_DIM)
#define SEL_WORDS (IN_DIM / 32)      // 16 words per o-row

__device__ uint32_t g_sel[OUT_DIM * SEL_WORDS];   // selection bitmask
__device__ uint32_t g_topk[B_DIM * 64];           // sorted top-64 keys per b-row

// ---------------- Threefry-2x32 (constexpr) --------------------------------
struct TF2 { uint32_t a, b; };

__host__ __device__ constexpr uint32_t rotl32(uint32_t v, int r) {
    return (v << r) | (v >> (32 - r));
}

__host__ __device__ constexpr TF2 tf2x32(uint32_t k0, uint32_t k1,
                                         uint32_t x0, uint32_t x1) {
    uint32_t k2 = k0 ^ k1 ^ 0x1BD11BDAu;
    x0 += k0; x1 += k1;
    x0 += x1; x1 = rotl32(x1, 13) ^ x0;
    x0 += x1; x1 = rotl32(x1, 15) ^ x0;
    x0 += x1; x1 = rotl32(x1, 26) ^ x0;
    x0 += x1; x1 = rotl32(x1,  6) ^ x0;
    x0 += k1; x1 += k2 + 1u;
    x0 += x1; x1 = rotl32(x1, 17) ^ x0;
    x0 += x1; x1 = rotl32(x1, 29) ^ x0;
    x0 += x1; x1 = rotl32(x1, 16) ^ x0;
    x0 += x1; x1 = rotl32(x1, 24) ^ x0;
    x0 += k2; x1 += k0 + 2u;
    x0 += x1; x1 = rotl32(x1, 13) ^ x0;
    x0 += x1; x1 = rotl32(x1, 15) ^ x0;
    x0 += x1; x1 = rotl32(x1, 26) ^ x0;
    x0 += x1; x1 = rotl32(x1,  6) ^ x0;
    x0 += k0; x1 += k1 + 3u;
    x0 += x1; x1 = rotl32(x1, 17) ^ x0;
    x0 += x1; x1 = rotl32(x1, 29) ^ x0;
    x0 += x1; x1 = rotl32(x1, 16) ^ x0;
    x0 += x1; x1 = rotl32(x1, 24) ^ x0;
    x0 += k1; x1 += k2 + 4u;
    x0 += x1; x1 = rotl32(x1, 13) ^ x0;
    x0 += x1; x1 = rotl32(x1, 15) ^ x0;
    x0 += x1; x1 = rotl32(x1, 26) ^ x0;
    x0 += x1; x1 = rotl32(x1,  6) ^ x0;
    x0 += k2; x1 += k0 + 5u;
    return TF2{x0, x1};
}

constexpr TF2 KB = tf2x32(0u, 42u, 0u, 0u);   // k_bern (foldlike split of key 42)

// ---------------- 1) selection bitmask --------------------------------------
__global__ __launch_bounds__(256) void mask_kernel(const float* __restrict__ pw) {
    uint32_t n = blockIdx.x * 256u + threadIdx.x;   // flat edge o*512+i

    TF2 r = tf2x32(KB.a, KB.b, 0u, n);
    uint32_t bits = r.a ^ r.b;
    float u = __uint_as_float((bits >> 9) | 0x3F800000u) - 1.0f;

    // selected <=> u * (1 + exp(wx - wy)) < 1
    float2 w = reinterpret_cast<const float2*>(pw)[n];
    float d = w.x - w.y;                       // in (-1, 1)
    float t = u * (1.0f + __expf(d));          // |error| <~ 1.5e-6
    bool sel;
    if (t < 1.0f - 1e-5f)      sel = true;
    else if (t > 1.0f + 1e-5f) sel = false;
    else {                                     // ~3 threads total: exact fp64
        double e = exp((double)w.x - (double)w.y);
        sel = ((double)u) * (1.0 + e) < 1.0;
    }

    uint32_t word = __ballot_sync(0xFFFFFFFFu, sel);
    if ((threadIdx.x & 31u) == 0u) g_sel[n >> 5] = word;
}

// ---------------- 2) per-row bitonic sort (u32 keys), emit top-64 -----------
// key = (valbits>>7)<<9 | idx : monotone in value (128-ulp ties), idx in low 9.
__global__ __launch_bounds__(256) void sort_kernel(const float* __restrict__ x) {
    __shared__ uint32_t keys[512];
    const int row = blockIdx.x;
    const int t = threadIdx.x;

    for (int i = t; i < 512; i += 256) {
        uint32_t vb = __float_as_uint(x[row * IN_DIM + i]);   // < 0x3F800000
        keys[i] = ((vb >> 7) << 9) | (uint32_t)i;
    }
    __syncthreads();

#define STAGE(J, K) { int i = 2 * t - (t & ((J) - 1)); int p = i | (J);       \
        uint32_t a = keys[i], b = keys[p];                                    \
        if ((a > b) == ((i & (K)) == 0)) { keys[i] = b; keys[p] = a; } }

    // k = 2..64: stages j<=32 are warp-local (warp w owns elements [64w,64w+64))
#pragma unroll
    for (int k = 2; k <= 64; k <<= 1) {
#pragma unroll
        for (int j = k >> 1; j > 0; j >>= 1) { STAGE(j, k) __syncwarp(); }
    }
    // k = 128
    __syncthreads(); STAGE(64, 128) __syncthreads();
#pragma unroll
    for (int j = 32; j > 0; j >>= 1) { STAGE(j, 128) __syncwarp(); }
    // k = 256
    __syncthreads(); STAGE(128, 256) __syncthreads(); STAGE(64, 256) __syncthreads();
#pragma unroll
    for (int j = 32; j > 0; j >>= 1) { STAGE(j, 256) __syncwarp(); }
    // k = 512
    __syncthreads(); STAGE(256, 512) __syncthreads(); STAGE(128, 512)
    __syncthreads(); STAGE(64, 512)  __syncthreads();
#pragma unroll
    for (int j = 32; j > 0; j >>= 1) { STAGE(j, 512) __syncwarp(); }
#undef STAGE

    __syncthreads();
    if (t < 64) g_topk[row * 64 + t] = keys[t];
}

// ---------------- 3) gather: first selected index in sorted order -----------
// CTA covers 8 b-rows x 256 o-cols; grid (2, 64). Exact values from smem x.
__global__ __launch_bounds__(256) void gather_kernel(
    const float* __restrict__ x, float* __restrict__ out) {
    __shared__ uint32_t s_sel[256][SEL_WORDS + 1];   // pad -> conflict-free
    __shared__ uint32_t s_keys[8][64];
    __shared__ float    s_x[8][IN_DIM];

    const int ob = blockIdx.x * 256;
    const int bb = blockIdx.y * 8;
    const int t = threadIdx.x;

#pragma unroll
    for (int q = 0; q < 16; ++q) {                   // 256 sel rows, coalesced
        int flat = q * 256 + t;
        s_sel[flat >> 4][flat & 15] = g_sel[ob * SEL_WORDS + flat];
    }
#pragma unroll
    for (int q = 0; q < 16; ++q) {                   // 8 x rows
        int flat = q * 256 + t;
        s_x[flat >> 9][flat & 511] = x[(bb + (flat >> 9)) * IN_DIM + (flat & 511)];
    }
#pragma unroll
    for (int q = 0; q < 2; ++q) {                    // 8 rows of top-64 keys
        int flat = q * 256 + t;
        s_keys[flat >> 6][flat & 63] = g_topk[(bb + (flat >> 6)) * 64 + (flat & 63)];
    }
    __syncthreads();

    const uint32_t* selrow = s_sel[t];               // this thread's o-row
    const int o = ob + t;

#pragma unroll 1
    for (int bi = 0; bi < 8; ++bi) {
        float res;
        bool found = false;
        for (int j = 0; j < 64; ++j) {               // expected ~2 iterations
            uint32_t idx = s_keys[bi][j] & 511u;
            if ((selrow[idx >> 5] >> (idx & 31u)) & 1u) {
                res = s_x[bi][idx];                  // exact value
                found = true;
                break;
            }
        }
        if (!found) {                                // P ~ 2e-9: exact dense scan
            float best = INFINITY, ball = INFINITY;
            for (int i = 0; i < IN_DIM; ++i) {
                float v = s_x[bi][i];
                ball = fminf(ball, v);
                if ((selrow[i >> 5] >> (i & 31u)) & 1u) best = fminf(best, v);
            }
            res = isinf(best) ? ball + 1.0f : best;  // zero-selected: impossible
        }
        out[(bb + bi) * OUT_DIM + o] = res;
    }
}

// ---------------------------------------------------------------------------
extern "C" void kernel_launch(void* const* d_in, const int* in_sizes, int n_in,
                              void* d_out, int out_size) {
    const float* x  = (const float*)d_in[0];   // [512, 512]
    const float* pw = (const float*)d_in[1];   // [512, 512, 2]
    float* out      = (float*)d_out;           // [512, 512]

    mask_kernel<<<N_EDGES / 256, 256>>>(pw);
    sort_kernel<<<B_DIM, 256>>>(x);
    dim3 ggrid(OUT_DIM / 256, B_DIM / 8);
    gather_kernel<<<ggrid, 256>>>(x, out);
}

// round 5
// speedup vs baseline: 3.4806x; 1.3125x over previous
#include <cuda_runtime.h>
#include <stdint.h>
#include <math.h>

// ---------------------------------------------------------------------------
// out[b,o] = min_i ( x[b,i] + mask[o,i] ),  B=IN=OUT=512,  x in [0,1)
// mask in {0,1}  =>  out[b,o] = min over SELECTED i of x[b,i]  (sparse min).
// Selection = JAX threefry bernoulli (partitionable variant, validated R2-R4).
// ---------------------------------------------------------------------------

#define B_DIM   512
#define IN_DIM  512
#define OUT_DIM 512
#define SEL_WORDS (IN_DIM / 32)     // 16 words per o-row

__device__ uint32_t g_sel[OUT_DIM * SEL_WORDS];   // selection bitmask
__device__ uint32_t g_topk[B_DIM * 64];           // sorted top-64 keys per b-row

// ---------------- Threefry-2x32 (constexpr) --------------------------------
struct TF2 { uint32_t a, b; };

__host__ __device__ constexpr uint32_t rotl32(uint32_t v, int r) {
    return (v << r) | (v >> (32 - r));
}

__host__ __device__ constexpr TF2 tf2x32(uint32_t k0, uint32_t k1,
                                         uint32_t x0, uint32_t x1) {
    uint32_t k2 = k0 ^ k1 ^ 0x1BD11BDAu;
    x0 += k0; x1 += k1;
    x0 += x1; x1 = rotl32(x1, 13) ^ x0;
    x0 += x1; x1 = rotl32(x1, 15) ^ x0;
    x0 += x1; x1 = rotl32(x1, 26) ^ x0;
    x0 += x1; x1 = rotl32(x1,  6) ^ x0;
    x0 += k1; x1 += k2 + 1u;
    x0 += x1; x1 = rotl32(x1, 17) ^ x0;
    x0 += x1; x1 = rotl32(x1, 29) ^ x0;
    x0 += x1; x1 = rotl32(x1, 16) ^ x0;
    x0 += x1; x1 = rotl32(x1, 24) ^ x0;
    x0 += k2; x1 += k0 + 2u;
    x0 += x1; x1 = rotl32(x1, 13) ^ x0;
    x0 += x1; x1 = rotl32(x1, 15) ^ x0;
    x0 += x1; x1 = rotl32(x1, 26) ^ x0;
    x0 += x1; x1 = rotl32(x1,  6) ^ x0;
    x0 += k0; x1 += k1 + 3u;
    x0 += x1; x1 = rotl32(x1, 17) ^ x0;
    x0 += x1; x1 = rotl32(x1, 29) ^ x0;
    x0 += x1; x1 = rotl32(x1, 16) ^ x0;
    x0 += x1; x1 = rotl32(x1, 24) ^ x0;
    x0 += k1; x1 += k2 + 4u;
    x0 += x1; x1 = rotl32(x1, 13) ^ x0;
    x0 += x1; x1 = rotl32(x1, 15) ^ x0;
    x0 += x1; x1 = rotl32(x1, 26) ^ x0;
    x0 += x1; x1 = rotl32(x1,  6) ^ x0;
    x0 += k2; x1 += k0 + 5u;
    return TF2{x0, x1};
}

constexpr TF2 KB = tf2x32(0u, 42u, 0u, 0u);   // k_bern (foldlike split of key 42)

// ---------------- bernoulli decision (validated) -----------------------------
__device__ __forceinline__ bool edge_selected(const float2 w, uint32_t n) {
    TF2 r = tf2x32(KB.a, KB.b, 0u, n);
    uint32_t bits = r.a ^ r.b;
    float u = __uint_as_float((bits >> 9) | 0x3F800000u) - 1.0f;
    float t = u * (1.0f + __expf(w.x - w.y));
    if (t < 1.0f - 1e-5f) return true;
    if (t > 1.0f + 1e-5f) return false;
    double e = exp((double)w.x - (double)w.y);       // boundary: exact fp64
    return ((double)u) * (1.0 + e) < 1.0;
}

// ---------------- bitonic helpers (2 elems/thread: e0=2t, e1=2t+1) ----------
// keep-min iff (ascending-dir == is-lower-element)
#define BSWAP(A, PA, KEEPMIN) ((KEEPMIN) ? umin((A),(PA)) : umax((A),(PA)))

// in-thread stage j=1
#define STAGE_J1(K) {                                                         \
    bool dir = (((2*t) & (K)) == 0);                                          \
    uint32_t lo = umin(a, b), hi = umax(a, b);                                \
    a = dir ? lo : hi; b = dir ? hi : lo; }

// shfl stage, 2 <= J <= 32
#define STAGE_SHFL(J, K) {                                                    \
    uint32_t pa = __shfl_xor_sync(0xFFFFFFFFu, a, (J) >> 1);                  \
    uint32_t pb = __shfl_xor_sync(0xFFFFFFFFu, b, (J) >> 1);                  \
    bool dir = (((2*t) & (K)) == 0);                                          \
    bool lower = ((t & ((J) >> 1)) == 0);                                     \
    bool km = (dir == lower);                                                 \
    a = BSWAP(a, pa, km); b = BSWAP(b, pb, km); }

// smem stage, J >= 64 (cross-warp)
#define STAGE_SMEM(J, K) {                                                    \
    __syncthreads();                                                          \
    sk[2*t] = a; sk[2*t+1] = b;                                               \
    __syncthreads();                                                          \
    uint32_t pa = sk[(2*t) ^ (J)];                                            \
    uint32_t pb = sk[(2*t+1) ^ (J)];                                          \
    bool dir = (((2*t) & (K)) == 0);                                          \
    bool lower = (((2*t) & (J)) == 0);                                        \
    bool km = (dir == lower);                                                 \
    a = BSWAP(a, pa, km); b = BSWAP(b, pb, km); }

#define TAIL32(K) STAGE_SHFL(32,K) STAGE_SHFL(16,K) STAGE_SHFL(8,K) \
                  STAGE_SHFL(4,K)  STAGE_SHFL(2,K)  STAGE_J1(K)

// ---------------- 1) combined mask + sort (block-divergent grid) ------------
// blocks [0,512): sort b-row;  blocks [512,1024): mask o-row.
__global__ __launch_bounds__(256) void prep_kernel(
    const float* __restrict__ x, const float* __restrict__ pw) {
    __shared__ uint32_t sk[512];
    const int t = threadIdx.x;

    if (blockIdx.x >= 512) {
        // ---- mask half: 2 independent threefry chains per thread (ILP=2)
        const uint32_t row = blockIdx.x - 512;
        const uint32_t n0 = row * 512u + t;          // word t/32
        const uint32_t n1 = n0 + 256u;               // word t/32 + 8
        float2 w0 = reinterpret_cast<const float2*>(pw)[n0];
        float2 w1 = reinterpret_cast<const float2*>(pw)[n1];
        bool s0 = edge_selected(w0, n0);
        bool s1 = edge_selected(w1, n1);
        uint32_t m0 = __ballot_sync(0xFFFFFFFFu, s0);
        uint32_t m1 = __ballot_sync(0xFFFFFFFFu, s1);
        if ((t & 31) == 0) {
            g_sel[(n0 >> 5)] = m0;
            g_sel[(n1 >> 5)] = m1;
        }
        return;
    }

    // ---- sort half: bitonic on 512 keys, 2 per thread in registers
    const int row = blockIdx.x;
    float2 xv = reinterpret_cast<const float2*>(x + row * IN_DIM)[t];
    // key = (valbits>>7)<<9 | idx  (monotone in value; exact value re-read later)
    uint32_t a = ((__float_as_uint(xv.x) >> 7) << 9) | (uint32_t)(2*t);
    uint32_t b = ((__float_as_uint(xv.y) >> 7) << 9) | (uint32_t)(2*t+1);

    // k = 2..64 : registers + shfl only
    STAGE_J1(2)
    STAGE_SHFL(2,4)  STAGE_J1(4)
    STAGE_SHFL(4,8)  STAGE_SHFL(2,8)  STAGE_J1(8)
    STAGE_SHFL(8,16) STAGE_SHFL(4,16) STAGE_SHFL(2,16) STAGE_J1(16)
    STAGE_SHFL(16,32) STAGE_SHFL(8,32) STAGE_SHFL(4,32) STAGE_SHFL(2,32) STAGE_J1(32)
    STAGE_SHFL(32,64) STAGE_SHFL(16,64) STAGE_SHFL(8,64) STAGE_SHFL(4,64)
    STAGE_SHFL(2,64)  STAGE_J1(64)
    // k = 128
    STAGE_SMEM(64,128)  TAIL32(128)
    // k = 256
    STAGE_SMEM(128,256) STAGE_SMEM(64,256) TAIL32(256)
    // k = 512
    STAGE_SMEM(256,512) STAGE_SMEM(128,512) STAGE_SMEM(64,512) TAIL32(512)

    if (t < 32) {                      // threads 0..31 hold sorted elems 0..63
        g_topk[row * 64 + 2*t]     = a;
        g_topk[row * 64 + 2*t + 1] = b;
    }
}

// ---------------- 2) gather: first selected index in sorted order -----------
// CTA covers 8 b-rows x 256 o-cols; grid (2, 64). Exact values from smem x.
__global__ __launch_bounds__(256) void gather_kernel(
    const float* __restrict__ x, float* __restrict__ out) {
    __shared__ uint32_t s_sel[256][SEL_WORDS + 1];
    __shared__ uint32_t s_keys[8][64];
    __shared__ float    s_x[8][IN_DIM];

    const int ob = blockIdx.x * 256;
    const int bb = blockIdx.y * 8;
    const int t = threadIdx.x;

#pragma unroll
    for (int q = 0; q < 16; ++q) {                  // 256 sel rows (coalesced)
        int flat = q * 256 + t;
        s_sel[flat >> 4][flat & 15] = g_sel[ob * SEL_WORDS + flat];
    }
#pragma unroll
    for (int q = 0; q < 16; ++q) {                  // 8 x rows
        int flat = q * 256 + t;
        s_x[flat >> 9][flat & 511] = x[(bb + (flat >> 9)) * IN_DIM + (flat & 511)];
    }
#pragma unroll
    for (int q = 0; q < 2; ++q) {                   // 8 rows of top-64 keys
        int flat = q * 256 + t;
        s_keys[flat >> 6][flat & 63] = g_topk[(bb + (flat >> 6)) * 64 + (flat & 63)];
    }
    __syncthreads();

    const uint32_t* selrow = s_sel[t];
    const int o = ob + t;

#pragma unroll 1
    for (int bi = 0; bi < 8; ++bi) {
        float res;
        bool found = false;
        for (int j = 0; j < 64; ++j) {              // expected ~2 iterations
            uint32_t idx = s_keys[bi][j] & 511u;
            if ((selrow[idx >> 5] >> (idx & 31u)) & 1u) {
                res = s_x[bi][idx];                 // exact value
                found = true;
                break;
            }
        }
        if (!found) {                               // P ~ 2e-9: exact dense scan
            float best = INFINITY, ball = INFINITY;
            for (int i = 0; i < IN_DIM; ++i) {
                float v = s_x[bi][i];
                ball = fminf(ball, v);
                if ((selrow[i >> 5] >> (i & 31u)) & 1u) best = fminf(best, v);
            }
            res = isinf(best) ? ball + 1.0f : best;
        }
        out[(bb + bi) * OUT_DIM + o] = res;
    }
}

// ---------------------------------------------------------------------------
extern "C" void kernel_launch(void* const* d_in, const int* in_sizes, int n_in,
                              void* d_out, int out_size) {
    const float* x  = (const float*)d_in[0];   // [512, 512]
    const float* pw = (const float*)d_in[1];   // [512, 512, 2]
    float* out      = (float*)d_out;           // [512, 512]

    prep_kernel<<<1024, 256>>>(x, pw);
    dim3 ggrid(OUT_DIM / 256, B_DIM / 8);
    gather_kernel<<<ggrid, 256>>>(x, out);
}

// round 6
// speedup vs baseline: 4.0476x; 1.1629x over previous
#include <cuda_runtime.h>
#include <stdint.h>
#include <math.h>

// ---------------------------------------------------------------------------
// out[b,o] = min_i ( x[b,i] + mask[o,i] ),  B=IN=OUT=512,  x in [0,1)
// mask in {0,1}  =>  out[b,o] = min over SELECTED i of x[b,i]  (sparse min).
// Selection = JAX threefry bernoulli (partitionable variant, validated R2-R5).
// ---------------------------------------------------------------------------

#define B_DIM   512
#define IN_DIM  512
#define OUT_DIM 512
#define SEL_WORDS (IN_DIM / 32)     // 16 words per o-row

__device__ uint32_t g_sel[OUT_DIM * SEL_WORDS];   // selection bitmask (32KB)
__device__ uint2    g_top[B_DIM * 64];            // (idx, exact valbits) sorted

// ---------------- Threefry-2x32 (constexpr) --------------------------------
struct TF2 { uint32_t a, b; };

__host__ __device__ constexpr uint32_t rotl32(uint32_t v, int r) {
    return (v << r) | (v >> (32 - r));
}

__host__ __device__ constexpr TF2 tf2x32(uint32_t k0, uint32_t k1,
                                         uint32_t x0, uint32_t x1) {
    uint32_t k2 = k0 ^ k1 ^ 0x1BD11BDAu;
    x0 += k0; x1 += k1;
    x0 += x1; x1 = rotl32(x1, 13) ^ x0;
    x0 += x1; x1 = rotl32(x1, 15) ^ x0;
    x0 += x1; x1 = rotl32(x1, 26) ^ x0;
    x0 += x1; x1 = rotl32(x1,  6) ^ x0;
    x0 += k1; x1 += k2 + 1u;
    x0 += x1; x1 = rotl32(x1, 17) ^ x0;
    x0 += x1; x1 = rotl32(x1, 29) ^ x0;
    x0 += x1; x1 = rotl32(x1, 16) ^ x0;
    x0 += x1; x1 = rotl32(x1, 24) ^ x0;
    x0 += k2; x1 += k0 + 2u;
    x0 += x1; x1 = rotl32(x1, 13) ^ x0;
    x0 += x1; x1 = rotl32(x1, 15) ^ x0;
    x0 += x1; x1 = rotl32(x1, 26) ^ x0;
    x0 += x1; x1 = rotl32(x1,  6) ^ x0;
    x0 += k0; x1 += k1 + 3u;
    x0 += x1; x1 = rotl32(x1, 17) ^ x0;
    x0 += x1; x1 = rotl32(x1, 29) ^ x0;
    x0 += x1; x1 = rotl32(x1, 16) ^ x0;
    x0 += x1; x1 = rotl32(x1, 24) ^ x0;
    x0 += k1; x1 += k2 + 4u;
    x0 += x1; x1 = rotl32(x1, 13) ^ x0;
    x0 += x1; x1 = rotl32(x1, 15) ^ x0;
    x0 += x1; x1 = rotl32(x1, 26) ^ x0;
    x0 += x1; x1 = rotl32(x1,  6) ^ x0;
    x0 += k2; x1 += k0 + 5u;
    return TF2{x0, x1};
}

constexpr TF2 KB = tf2x32(0u, 42u, 0u, 0u);   // k_bern (foldlike split of key 42)

// ---------------- bernoulli decision (validated) -----------------------------
__device__ __forceinline__ bool edge_selected(const float2 w, uint32_t n) {
    TF2 r = tf2x32(KB.a, KB.b, 0u, n);
    uint32_t bits = r.a ^ r.b;
    float u = __uint_as_float((bits >> 9) | 0x3F800000u) - 1.0f;
    float t = u * (1.0f + __expf(w.x - w.y));
    if (t < 1.0f - 1e-5f) return true;
    if (t > 1.0f + 1e-5f) return false;
    double e = exp((double)w.x - (double)w.y);       // boundary: exact fp64
    return ((double)u) * (1.0 + e) < 1.0;
}

// ---------------- bitonic helpers (2 elems/thread: e0=2t, e1=2t+1) ----------
#define BSWAP(A, PA, KEEPMIN) ((KEEPMIN) ? umin((A),(PA)) : umax((A),(PA)))

#define STAGE_J1(K) {                                                         \
    bool dir = (((2*t) & (K)) == 0);                                          \
    uint32_t lo = umin(a, b), hi = umax(a, b);                                \
    a = dir ? lo : hi; b = dir ? hi : lo; }

#define STAGE_SHFL(J, K) {                                                    \
    uint32_t pa = __shfl_xor_sync(0xFFFFFFFFu, a, (J) >> 1);                  \
    uint32_t pb = __shfl_xor_sync(0xFFFFFFFFu, b, (J) >> 1);                  \
    bool dir = (((2*t) & (K)) == 0);                                          \
    bool lower = ((t & ((J) >> 1)) == 0);                                     \
    bool km = (dir == lower);                                                 \
    a = BSWAP(a, pa, km); b = BSWAP(b, pb, km); }

#define STAGE_SMEM(J, K) {                                                    \
    __syncthreads();                                                          \
    sk[2*t] = a; sk[2*t+1] = b;                                               \
    __syncthreads();                                                          \
    uint32_t pa = sk[(2*t) ^ (J)];                                            \
    uint32_t pb = sk[(2*t+1) ^ (J)];                                          \
    bool dir = (((2*t) & (K)) == 0);                                          \
    bool lower = (((2*t) & (J)) == 0);                                        \
    bool km = (dir == lower);                                                 \
    a = BSWAP(a, pa, km); b = BSWAP(b, pb, km); }

#define TAIL32(K) STAGE_SHFL(32,K) STAGE_SHFL(16,K) STAGE_SHFL(8,K) \
                  STAGE_SHFL(4,K)  STAGE_SHFL(2,K)  STAGE_J1(K)

// ---------------- 1) combined mask + sort (block-divergent grid) ------------
// blocks [0,512): sort b-row;  blocks [512,1024): mask o-row.
__global__ __launch_bounds__(256) void prep_kernel(
    const float* __restrict__ x, const float* __restrict__ pw) {
    __shared__ uint32_t sk[512];
    __shared__ float s_xv[512];
    const int t = threadIdx.x;

    if (blockIdx.x >= 512) {
        // ---- mask half: 2 independent threefry chains per thread (ILP=2)
        const uint32_t row = blockIdx.x - 512;
        const uint32_t n0 = row * 512u + t;
        const uint32_t n1 = n0 + 256u;
        float2 w0 = reinterpret_cast<const float2*>(pw)[n0];
        float2 w1 = reinterpret_cast<const float2*>(pw)[n1];
        bool s0 = edge_selected(w0, n0);
        bool s1 = edge_selected(w1, n1);
        uint32_t m0 = __ballot_sync(0xFFFFFFFFu, s0);
        uint32_t m1 = __ballot_sync(0xFFFFFFFFu, s1);
        if ((t & 31) == 0) {
            g_sel[(n0 >> 5)] = m0;
            g_sel[(n1 >> 5)] = m1;
        }
        return;
    }

    // ---- sort half: bitonic on 512 keys, 2 per thread in registers
    const int row = blockIdx.x;
    float2 xv = reinterpret_cast<const float2*>(x + row * IN_DIM)[t];
    s_xv[2*t]   = xv.x;                        // exact values for final emit
    s_xv[2*t+1] = xv.y;
    // key = (valbits>>7)<<9 | idx  (monotone in value, 128-ulp ties)
    uint32_t a = ((__float_as_uint(xv.x) >> 7) << 9) | (uint32_t)(2*t);
    uint32_t b = ((__float_as_uint(xv.y) >> 7) << 9) | (uint32_t)(2*t+1);

    // k = 2..64 : registers + shfl only
    STAGE_J1(2)
    STAGE_SHFL(2,4)  STAGE_J1(4)
    STAGE_SHFL(4,8)  STAGE_SHFL(2,8)  STAGE_J1(8)
    STAGE_SHFL(8,16) STAGE_SHFL(4,16) STAGE_SHFL(2,16) STAGE_J1(16)
    STAGE_SHFL(16,32) STAGE_SHFL(8,32) STAGE_SHFL(4,32) STAGE_SHFL(2,32) STAGE_J1(32)
    STAGE_SHFL(32,64) STAGE_SHFL(16,64) STAGE_SHFL(8,64) STAGE_SHFL(4,64)
    STAGE_SHFL(2,64)  STAGE_J1(64)
    // k = 128 / 256 / 512 (cross-warp via smem; barriers also fence s_xv)
    STAGE_SMEM(64,128)  TAIL32(128)
    STAGE_SMEM(128,256) STAGE_SMEM(64,256) TAIL32(256)
    STAGE_SMEM(256,512) STAGE_SMEM(128,512) STAGE_SMEM(64,512) TAIL32(512)

    if (t < 32) {                      // threads 0..31 hold sorted elems 0..63
        uint32_t ia = a & 511u, ib = b & 511u;
        g_top[row * 64 + 2*t]     = make_uint2(ia, __float_as_uint(s_xv[ia]));
        g_top[row * 64 + 2*t + 1] = make_uint2(ib, __float_as_uint(s_xv[ib]));
    }
}

// ---------------- 2) gather: first selected index in sorted order -----------
// One CTA per b-row (512 CTAs, 256 threads, ~0.5KB smem -> high occupancy).
// sel words read straight from g_sel (32KB total, L1-resident).
__global__ __launch_bounds__(256) void gather_kernel(
    const float* __restrict__ x, float* __restrict__ out) {
    __shared__ uint32_t s_idx[64];
    __shared__ float    s_val[64];

    const int b = blockIdx.x;
    const int t = threadIdx.x;

    if (t < 64) {
        uint2 kv = g_top[b * 64 + t];
        s_idx[t] = kv.x;
        s_val[t] = __uint_as_float(kv.y);
    }
    __syncthreads();

#pragma unroll 1
    for (int oo = 0; oo < 2; ++oo) {
        const int o = oo * 256 + t;
        const uint32_t* __restrict__ sel = g_sel + o * SEL_WORDS;
        float res;
        bool found = false;
        for (int j = 0; j < 64; ++j) {              // expected ~2 iterations
            uint32_t idx = s_idx[j];
            if ((sel[idx >> 5] >> (idx & 31u)) & 1u) {
                res = s_val[j];                     // exact value
                found = true;
                break;
            }
        }
        if (!found) {                               // P ~ 2e-9: exact dense scan
            float best = INFINITY, ball = INFINITY;
            const float* xr = x + b * IN_DIM;
            for (int i = 0; i < IN_DIM; ++i) {
                float v = xr[i];
                ball = fminf(ball, v);
                if ((sel[i >> 5] >> (i & 31u)) & 1u) best = fminf(best, v);
            }
            res = isinf(best) ? ball + 1.0f : best; // zero-selected: impossible
        }
        out[b * OUT_DIM + o] = res;
    }
}

// ---------------------------------------------------------------------------
extern "C" void kernel_launch(void* const* d_in, const int* in_sizes, int n_in,
                              void* d_out, int out_size) {
    const float* x  = (const float*)d_in[0];   // [512, 512]
    const float* pw = (const float*)d_in[1];   // [512, 512, 2]
    float* out      = (float*)d_out;           // [512, 512]

    prep_kernel<<<1024, 256>>>(x, pw);
    gather_kernel<<<B_DIM, 256>>>(x, out);
}